// round 1
// baseline (speedup 1.0000x reference)
#include <cuda_runtime.h>
#include <cuda_bf16.h>

#define NNODES 100000
#define NEDGES 1600000
#define DIM 64
#define NEG_SLOPE 0.2f
#define BN_EPS 1e-5f

// ---------------- scratch (device globals; no allocation allowed) ----------
__device__ float  g_feat[NNODES * DIM];   // W-projected features of current layer
__device__ float  g_acc [NNODES * DIM];   // scatter accumulator (pre-BN output)
__device__ float  g_h   [NNODES * DIM];   // inter-layer hidden state
__device__ float  g_el  [NNODES];
__device__ float  g_er  [NNODES];
__device__ float  g_s   [NNODES];         // softmax denominator per dst
__device__ float  g_sinv[NNODES];
__device__ float  g_ex  [NEDGES];         // exp(leakyrelu(e)) per edge
__device__ double g_bnsum[DIM];
__device__ double g_bnsq [DIM];
__device__ float  g_scale[DIM];
__device__ float  g_shift[DIM];

// ---------------- K1: feat = h @ W ; el = feat@al ; er = feat@ar -----------
// Also zeroes g_acc rows, g_s rows, and (block 0) the BN sums.
// Block: 256 threads handle 64 rows. thread t: colgroup cg=t&15 (4 cols),
// rowgroup rg=t>>4 (4 rows). W and h tile staged in smem.
__global__ void k_gemm(const float* __restrict__ hin_ext, int use_gh,
                       const float* __restrict__ W,
                       const float* __restrict__ al,
                       const float* __restrict__ ar,
                       int n) {
    __shared__ float Ws[DIM * DIM];
    __shared__ float hs[64 * DIM];
    __shared__ float als[DIM], ars[DIM];

    const float* hin = use_gh ? g_h : hin_ext;
    int t = threadIdx.x;
    int row0 = blockIdx.x * 64;

    for (int i = t; i < DIM * DIM / 4; i += 256)
        ((float4*)Ws)[i] = ((const float4*)W)[i];
    if (t < DIM) { als[t] = al[t]; ars[t] = ar[t]; }

    int nrows = n - row0; if (nrows > 64) nrows = 64;
    for (int i = t; i < nrows * (DIM / 4); i += 256)
        ((float4*)hs)[i] = ((const float4*)(hin + (size_t)row0 * DIM))[i];

    if (blockIdx.x == 0 && t < DIM) { g_bnsum[t] = 0.0; g_bnsq[t] = 0.0; }
    __syncthreads();

    int cg = t & 15, rg = t >> 4;
    float4 acc[4];
    #pragma unroll
    for (int r = 0; r < 4; r++) acc[r] = make_float4(0.f, 0.f, 0.f, 0.f);

    #pragma unroll 16
    for (int k = 0; k < DIM; k++) {
        float4 w = *(const float4*)(Ws + k * DIM + cg * 4);
        #pragma unroll
        for (int r = 0; r < 4; r++) {
            float hv = hs[(rg * 4 + r) * DIM + k];
            acc[r].x += hv * w.x;
            acc[r].y += hv * w.y;
            acc[r].z += hv * w.z;
            acc[r].w += hv * w.w;
        }
    }

    float4 alv = ((float4*)als)[cg];
    float4 arv = ((float4*)ars)[cg];
    #pragma unroll
    for (int r = 0; r < 4; r++) {
        int row = row0 + rg * 4 + r;
        float pl = acc[r].x * alv.x + acc[r].y * alv.y + acc[r].z * alv.z + acc[r].w * alv.w;
        float pr = acc[r].x * arv.x + acc[r].y * arv.y + acc[r].z * arv.z + acc[r].w * arv.w;
        // reduce over the 16 colgroups (contiguous 16-lane halves of the warp)
        #pragma unroll
        for (int off = 8; off > 0; off >>= 1) {
            pl += __shfl_xor_sync(0xffffffffu, pl, off);
            pr += __shfl_xor_sync(0xffffffffu, pr, off);
        }
        if (row < n) {
            *(float4*)(g_feat + (size_t)row * DIM + cg * 4) = acc[r];
            *(float4*)(g_acc  + (size_t)row * DIM + cg * 4) = make_float4(0.f, 0.f, 0.f, 0.f);
            if (cg == 0) { g_el[row] = pl; g_er[row] = pr; g_s[row] = 0.f; }
        }
    }
}

// ---------------- K2: per-edge exp(leakyrelu(el[src]+er[dst])), sum to dst --
// Softmax max-shift is skipped: shift-invariant, and |e| is O(10) here so
// exp() cannot overflow; matches reference up to float rounding.
__global__ void k_edge_exp(const int* __restrict__ src,
                           const int* __restrict__ dst, int E) {
    int e = blockIdx.x * blockDim.x + threadIdx.x;
    if (e >= E) return;
    int di = dst[e];
    float x = g_el[src[e]] + g_er[di];
    x = x > 0.f ? x : NEG_SLOPE * x;
    float ex = __expf(x);
    g_ex[e] = ex;
    atomicAdd(&g_s[di], ex);
}

// ---------------- K3: reciprocal of softmax denominator ---------------------
__global__ void k_inv(int n) {
    int i = blockIdx.x * blockDim.x + threadIdx.x;
    if (i < n) {
        float s = g_s[i];
        g_sinv[i] = (s > 0.f) ? 1.f / s : 0.f;
    }
}

// ---------------- K4: scatter acc[dst] += alpha * feat[src] -----------------
// 16 threads per edge, float4 vector atomics (sm_90+).
__global__ void k_scatter(const int* __restrict__ src,
                          const int* __restrict__ dst, int E) {
    int idx = blockIdx.x * blockDim.x + threadIdx.x;
    int e = idx >> 4;
    if (e >= E) return;
    int c = idx & 15;
    int si = src[e], di = dst[e];
    float coef = g_ex[e] * g_sinv[di];
    float4 f = *(const float4*)(g_feat + (size_t)si * DIM + c * 4);
    float4 v = make_float4(f.x * coef, f.y * coef, f.z * coef, f.w * coef);
    atomicAdd((float4*)(g_acc + (size_t)di * DIM + c * 4), v);
}

// ---------------- K5: BN column stats (sum, sumsq) --------------------------
__global__ void k_bnstats(int n) {
    int col  = threadIdx.x & 63;
    int rsub = threadIdx.x >> 6;       // 0..3
    float s1 = 0.f, s2 = 0.f;
    for (int r = blockIdx.x * 4 + rsub; r < n; r += gridDim.x * 4) {
        float v = g_acc[(size_t)r * DIM + col];
        s1 += v; s2 += v * v;
    }
    __shared__ float sh[512];
    sh[threadIdx.x] = s1;
    sh[256 + threadIdx.x] = s2;
    __syncthreads();
    if (threadIdx.x < 64) {
        float t1 = sh[threadIdx.x] + sh[threadIdx.x + 64] + sh[threadIdx.x + 128] + sh[threadIdx.x + 192];
        float t2 = sh[256 + threadIdx.x] + sh[256 + threadIdx.x + 64] +
                   sh[256 + threadIdx.x + 128] + sh[256 + threadIdx.x + 192];
        atomicAdd(&g_bnsum[col], (double)t1);
        atomicAdd(&g_bnsq [col], (double)t2);
    }
}

// ---------------- K5b: finalize per-column affine (bias b cancels in BN) ----
__global__ void k_bnfinal(const float* __restrict__ gma,
                          const float* __restrict__ beta, int n) {
    int c = threadIdx.x;
    if (c < DIM) {
        double inv_n = 1.0 / (double)n;
        double mu  = g_bnsum[c] * inv_n;
        double var = g_bnsq[c] * inv_n - mu * mu;
        float rs = rsqrtf((float)var + BN_EPS);
        float sc = rs * gma[c];
        g_scale[c] = sc;
        g_shift[c] = beta[c] - (float)mu * sc;
    }
}

// ---------------- K6: apply BN affine (+ optional ELU) ----------------------
__global__ void k_bnapply(float* __restrict__ out_ext, int use_gh,
                          int total4, int do_elu) {
    int idx4 = blockIdx.x * blockDim.x + threadIdx.x;
    if (idx4 >= total4) return;
    float* out = use_gh ? g_h : out_ext;
    int c = (idx4 & 15) * 4;
    float4 a = ((const float4*)g_acc)[idx4];
    float4 v;
    v.x = a.x * g_scale[c + 0] + g_shift[c + 0];
    v.y = a.y * g_scale[c + 1] + g_shift[c + 1];
    v.z = a.z * g_scale[c + 2] + g_shift[c + 2];
    v.w = a.w * g_scale[c + 3] + g_shift[c + 3];
    if (do_elu) {
        v.x = v.x > 0.f ? v.x : (__expf(v.x) - 1.f);
        v.y = v.y > 0.f ? v.y : (__expf(v.y) - 1.f);
        v.z = v.z > 0.f ? v.z : (__expf(v.z) - 1.f);
        v.w = v.w > 0.f ? v.w : (__expf(v.w) - 1.f);
    }
    ((float4*)out)[idx4] = v;
}

// ---------------- host ------------------------------------------------------
extern "C" void kernel_launch(void* const* d_in, const int* in_sizes, int n_in,
                              void* d_out, int out_size) {
    const float* node_w = (const float*)d_in[0];
    const int*   src    = (const int*)d_in[2];
    const int*   dst    = (const int*)d_in[3];
    int n = in_sizes[0] / DIM;
    int E = in_sizes[2];
    float* out = (float*)d_out;

    for (int layer = 0; layer < 3; layer++) {
        const float* W    = (const float*)d_in[4 + layer * 6 + 0];
        const float* al   = (const float*)d_in[4 + layer * 6 + 1];
        const float* ar   = (const float*)d_in[4 + layer * 6 + 2];
        // b = d_in[...+3] cancels exactly inside BatchNorm — never read.
        const float* gma  = (const float*)d_in[4 + layer * 6 + 4];
        const float* beta = (const float*)d_in[4 + layer * 6 + 5];

        int gemm_blocks = (n + 63) / 64;
        k_gemm<<<gemm_blocks, 256>>>(layer == 0 ? node_w : nullptr,
                                     layer != 0, W, al, ar, n);
        k_edge_exp<<<(E + 255) / 256, 256>>>(src, dst, E);
        k_inv<<<(n + 255) / 256, 256>>>(n);
        long long scat_threads = (long long)E * 16;
        k_scatter<<<(int)((scat_threads + 255) / 256), 256>>>(src, dst, E);
        k_bnstats<<<512, 256>>>(n);
        k_bnfinal<<<1, 64>>>(gma, beta, n);
        int total4 = n * DIM / 4;
        int last = (layer == 2);
        k_bnapply<<<(total4 + 255) / 256, 256>>>(last ? out : nullptr,
                                                 !last, total4, !last);
    }
}